// round 2
// baseline (speedup 1.0000x reference)
#include <cuda_runtime.h>

#define EPS_F 1e-16f
#define NEG_SLOPE 0.2f

static const int MAXN = 50048;
static const int MAXE = 850048;

// scratch (device globals — no allocation allowed)
__device__ int   g_src[MAXE];
__device__ int   g_dst[MAXE];
__device__ float g_ew[MAXE];
__device__ float g_h[(size_t)MAXN * 64];
__device__ float g_prev[(size_t)MAXN * 64];
__device__ float g_as[MAXN];
__device__ float g_ad[MAXN];
__device__ float g_s[MAXN];
__device__ float g_sinv[MAXN];
__device__ int   g_is64;

// ---------------------------------------------------------------------------
// Detect whether edge_index is int64 or int32 on device.
// If int64 (values < 2^31, nonneg), every odd 32-bit word is 0.
// ---------------------------------------------------------------------------
__global__ void detect_dtype(const int* __restrict__ ei32) {
    if (threadIdx.x == 0 && blockIdx.x == 0) {
        int all_zero = 1;
        #pragma unroll
        for (int k = 0; k < 64; k++)
            if (ei32[2 * k + 1] != 0) { all_zero = 0; break; }
        g_is64 = all_zero;
    }
}

// ---------------------------------------------------------------------------
// Build int32 edge arrays with self-loops appended; also emit the stacked
// (src,dst) index output (as float32) at the head of d_out.
// ---------------------------------------------------------------------------
__global__ void build_edges(const int* __restrict__ ei32, int E, int Ep, int n,
                            float* __restrict__ outIdx) {
    int e = blockIdx.x * blockDim.x + threadIdx.x;
    if (e >= Ep) return;
    int s, d;
    if (e < E) {
        if (g_is64) {
            const long long* ei = (const long long*)ei32;
            s = (int)ei[e]; d = (int)ei[E + e];
        } else {
            s = ei32[e]; d = ei32[E + e];
        }
    } else {
        s = d = e - E;
    }
    // clamp defensively: a bad index becomes wrong-answer, not a crash
    s = min(max(s, 0), n - 1);
    d = min(max(d, 0), n - 1);
    g_src[e] = s;
    g_dst[e] = d;
    outIdx[e]      = (float)s;
    outIdx[Ep + e] = (float)d;
}

// ---------------------------------------------------------------------------
// Fused GEMM: h = in @ W^T ; as = h . a_src ; ad = h . a_dst ; g_s = 0.
// If RB, input element k is relu(in[k] + bprev[k]) (prev layer bias+relu).
// in == nullptr means "read g_prev".
// One warp per row; W transposed in smem for conflict-free access.
// ---------------------------------------------------------------------------
template<int FIN, int FOUT, bool RB>
__global__ __launch_bounds__(256)
void gat_gemm(const float* __restrict__ in, const float* __restrict__ bprev,
              const float* __restrict__ W, const float* __restrict__ av,
              const float* __restrict__ dv, int n) {
    __shared__ float sWt[FIN * FOUT];   // transposed: sWt[k*FOUT + j]
    __shared__ float srow[8][FIN];
    __shared__ float sA[FOUT];
    __shared__ float sD[FOUT];
    __shared__ float sB[FIN];

    int tid = threadIdx.x;
    for (int i = tid; i < FIN * FOUT; i += 256) {
        int j = i / FIN, k = i % FIN;
        sWt[k * FOUT + j] = W[i];
    }
    if (tid < FOUT) { sA[tid] = av[tid]; sD[tid] = dv[tid]; }
    if (RB) {
        for (int i = tid; i < FIN; i += 256) sB[i] = bprev[i];
    }
    __syncthreads();

    const float* src_in = in ? in : g_prev;
    int w = tid >> 5, lane = tid & 31;

    for (int row = blockIdx.x * 8 + w; row < n; row += gridDim.x * 8) {
        const float* rp = src_in + (size_t)row * FIN;
        #pragma unroll
        for (int u = 0; u < FIN / 32; u++) {
            int k = u * 32 + lane;
            float v = rp[k];
            if (RB) v = fmaxf(v + sB[k], 0.f);
            srow[w][k] = v;
        }
        __syncwarp();

        float acc[FOUT / 32];
        #pragma unroll
        for (int c = 0; c < FOUT / 32; c++) acc[c] = 0.f;
        #pragma unroll
        for (int k = 0; k < FIN; k++) {
            float rv = srow[w][k];
            #pragma unroll
            for (int c = 0; c < FOUT / 32; c++)
                acc[c] += rv * sWt[k * FOUT + c * 32 + lane];
        }

        float pa = 0.f, pd = 0.f;
        #pragma unroll
        for (int c = 0; c < FOUT / 32; c++) {
            g_h[(size_t)row * FOUT + c * 32 + lane] = acc[c];
            pa += acc[c] * sA[c * 32 + lane];
            pd += acc[c] * sD[c * 32 + lane];
        }
        #pragma unroll
        for (int o = 16; o > 0; o >>= 1) {
            pa += __shfl_down_sync(0xffffffffu, pa, o);
            pd += __shfl_down_sync(0xffffffffu, pd, o);
        }
        if (lane == 0) { g_as[row] = pa; g_ad[row] = pd; g_s[row] = 0.f; }
        __syncwarp();
    }
}

// ---------------------------------------------------------------------------
// Per-edge: w = exp(leaky_relu(as[src] + ad[dst])); segment-sum into g_s.
// (Max-subtraction skipped: scores bounded, exp never overflows, and the
//  normalized alpha is mathematically identical.)
// ---------------------------------------------------------------------------
__global__ void edge_score(int ep) {
    int e = blockIdx.x * blockDim.x + threadIdx.x;
    if (e >= ep) return;
    int s = g_src[e], d = g_dst[e];
    float v = g_as[s] + g_ad[d];
    v = v > 0.f ? v : NEG_SLOPE * v;
    float w = expf(v);
    g_ew[e] = w;
    atomicAdd(&g_s[d], w);
}

// ---------------------------------------------------------------------------
// Init agg buffer (to 0 or to bias) and compute sinv = 1/(s + eps).
// aggOut == nullptr means "use g_prev".
// ---------------------------------------------------------------------------
template<int FOUT>
__global__ void prep_scatter(int n, float* aggOut, const float* __restrict__ bias) {
    int i = blockIdx.x * blockDim.x + threadIdx.x;
    float* agg = aggOut ? aggOut : g_prev;
    int total = n * FOUT;
    if (i < total) agg[i] = bias ? bias[i & (FOUT - 1)] : 0.f;
    if (i < n) g_sinv[i] = 1.f / (g_s[i] + EPS_F);
}

// ---------------------------------------------------------------------------
// Scatter-aggregate: agg[dst] += alpha * h[src]. FOUT threads per edge
// (coalesced gather + coalesced atomics). Optionally write alpha (layer 1).
// ---------------------------------------------------------------------------
template<int FOUT, bool WRITE_ALPHA>
__global__ void scatter_agg(int ep, float* aggOut, float* __restrict__ alphaOut) {
    long long t = (long long)blockIdx.x * blockDim.x + threadIdx.x;
    int e = (int)(t / FOUT);
    if (e >= ep) return;
    int f = (int)(t & (FOUT - 1));
    int s = g_src[e], d = g_dst[e];
    float alpha = g_ew[e] * g_sinv[d];
    float* agg = aggOut ? aggOut : g_prev;
    atomicAdd(&agg[(size_t)d * FOUT + f], alpha * g_h[(size_t)s * FOUT + f]);
    if (WRITE_ALPHA && f == 0) alphaOut[e] = alpha;
}

// ---------------------------------------------------------------------------

extern "C" void kernel_launch(void* const* d_in, const int* in_sizes, int n_in,
                              void* d_out, int out_size) {
    const float* x    = (const float*)d_in[0];
    const int*   ei32 = (const int*)d_in[1];
    const float* W1 = (const float*)d_in[2];
    const float* a1s = (const float*)d_in[3];
    const float* a1d = (const float*)d_in[4];
    const float* b1 = (const float*)d_in[5];
    const float* W2 = (const float*)d_in[6];
    const float* a2s = (const float*)d_in[7];
    const float* a2d = (const float*)d_in[8];
    const float* b2 = (const float*)d_in[9];
    const float* W3 = (const float*)d_in[10];
    const float* a3s = (const float*)d_in[11];
    const float* a3d = (const float*)d_in[12];
    const float* b3 = (const float*)d_in[13];

    const int N  = in_sizes[0] / 128;     // 50000
    const int E  = in_sizes[1] / 2;       // 800000 (element count, either dtype)
    const int Ep = E + N;                 // with self loops

    float* out      = (float*)d_out;
    float* outAlpha = out + 2 * (size_t)Ep;
    float* outO     = out + 3 * (size_t)Ep;

    const int TB = 256;
    int ebl = (Ep + TB - 1) / TB;

    detect_dtype<<<1, 32>>>(ei32);
    build_edges<<<ebl, TB>>>(ei32, E, Ep, N, out);

    // ---- layer 1: 128 -> 64 ----
    gat_gemm<128, 64, false><<<592, TB>>>(x, nullptr, W1, a1s, a1d, N);
    edge_score<<<ebl, TB>>>(Ep);
    prep_scatter<64><<<(N * 64 + TB - 1) / TB, TB>>>(N, nullptr, nullptr);
    scatter_agg<64, true><<<(int)(((long long)Ep * 64 + TB - 1) / TB), TB>>>(Ep, nullptr, outAlpha);

    // ---- layer 2: 64 -> 64 (input = relu(agg1 + b1)) ----
    gat_gemm<64, 64, true><<<592, TB>>>(nullptr, b1, W2, a2s, a2d, N);
    edge_score<<<ebl, TB>>>(Ep);
    prep_scatter<64><<<(N * 64 + TB - 1) / TB, TB>>>(N, nullptr, nullptr);
    scatter_agg<64, false><<<(int)(((long long)Ep * 64 + TB - 1) / TB), TB>>>(Ep, nullptr, nullptr);

    // ---- layer 3: 64 -> 32 (input = relu(agg2 + b2)), out = agg + b3 ----
    gat_gemm<64, 32, true><<<592, TB>>>(nullptr, b2, W3, a3s, a3d, N);
    edge_score<<<ebl, TB>>>(Ep);
    prep_scatter<32><<<(N * 32 + TB - 1) / TB, TB>>>(N, outO, b3);
    scatter_agg<32, false><<<(int)(((long long)Ep * 32 + TB - 1) / TB), TB>>>(Ep, outO, nullptr);
}

// round 3
// speedup vs baseline: 1.6156x; 1.6156x over previous
#include <cuda_runtime.h>

#define EPS_F 1e-16f
#define NEG_SLOPE 0.2f

static const int MAXN = 50048;
static const int MAXE = 850048;

// scratch (device globals — no allocation allowed)
__device__ __align__(16) int2  g_edge[MAXE];
__device__ float g_ew[MAXE];
__device__ __align__(16) float g_h[(size_t)MAXN * 64];
__device__ __align__(16) float g_aggA[(size_t)MAXN * 64];
__device__ __align__(16) float g_aggB[(size_t)MAXN * 64];
__device__ float g_as[MAXN];
__device__ float g_ad[MAXN];
__device__ float g_s[MAXN];
__device__ int   g_is64;

// ---------------------------------------------------------------------------
__device__ __forceinline__ void red_add_v4(float* addr, float a, float b,
                                           float c, float d) {
    asm volatile("red.global.add.v4.f32 [%0], {%1,%2,%3,%4};"
                 :: "l"(addr), "f"(a), "f"(b), "f"(c), "f"(d)
                 : "memory");
}

// ---------------------------------------------------------------------------
// Detect whether edge_index is int64 or int32 on device.
// ---------------------------------------------------------------------------
__global__ void detect_dtype(const int* __restrict__ ei32) {
    if (threadIdx.x == 0 && blockIdx.x == 0) {
        int all_zero = 1;
        #pragma unroll
        for (int k = 0; k < 64; k++)
            if (ei32[2 * k + 1] != 0) { all_zero = 0; break; }
        g_is64 = all_zero;
    }
}

// ---------------------------------------------------------------------------
// Build packed int2 edges with self-loops; emit stacked (src,dst) as float.
// ---------------------------------------------------------------------------
__global__ void build_edges(const int* __restrict__ ei32, int E, int Ep, int n,
                            float* __restrict__ outIdx) {
    int e = blockIdx.x * blockDim.x + threadIdx.x;
    if (e >= Ep) return;
    int s, d;
    if (e < E) {
        if (g_is64) {
            const long long* ei = (const long long*)ei32;
            s = (int)ei[e]; d = (int)ei[E + e];
        } else {
            s = ei32[e]; d = ei32[E + e];
        }
    } else {
        s = d = e - E;
    }
    s = min(max(s, 0), n - 1);
    d = min(max(d, 0), n - 1);
    g_edge[e] = make_int2(s, d);
    outIdx[e]      = (float)s;
    outIdx[Ep + e] = (float)d;
}

// ---------------------------------------------------------------------------
// Fused GEMM: h = in @ W^T ; as = h.a_src ; ad = h.a_dst.
// If RB: input element k is relu(in[k]*sinv_row + bprev[k]) where
// sinv_row = 1/(g_s[row]+eps)  (normalization of the previous layer's
// unnormalized aggregate, deferred to here).
// Also: zeroes g_s[row] (for this layer's segment sums) and zeroes the
// agg buffer rows this layer's scatter will accumulate into.
// INSEL: 0 = xin param, 1 = g_aggA, 2 = g_aggB.  ZSEL: 1 = A, 2 = B.
// ---------------------------------------------------------------------------
template<int FIN, int FOUT, bool RB, int INSEL, int ZSEL>
__global__ __launch_bounds__(256)
void gat_gemm(const float* __restrict__ xin, const float* __restrict__ bprev,
              const float* __restrict__ W, const float* __restrict__ av,
              const float* __restrict__ dv, int n) {
    __shared__ float sWt[FIN * FOUT];   // transposed: sWt[k*FOUT + j]
    __shared__ float srow[8][FIN];
    __shared__ float sA[FOUT];
    __shared__ float sD[FOUT];
    __shared__ float sB[FIN];

    int tid = threadIdx.x;
    for (int i = tid; i < FIN * FOUT; i += 256) {
        int j = i / FIN, k = i % FIN;
        sWt[k * FOUT + j] = W[i];
    }
    if (tid < FOUT) { sA[tid] = av[tid]; sD[tid] = dv[tid]; }
    if (RB) {
        for (int i = tid; i < FIN; i += 256) sB[i] = bprev[i];
    }
    __syncthreads();

    const float* src_in = (INSEL == 0) ? xin : (INSEL == 1 ? g_aggA : g_aggB);
    float* aggz = (ZSEL == 1) ? g_aggA : g_aggB;
    int w = tid >> 5, lane = tid & 31;

    for (int row = blockIdx.x * 8 + w; row < n; row += gridDim.x * 8) {
        const float* rp = src_in + (size_t)row * FIN;
        float sinv = RB ? (1.f / (g_s[row] + EPS_F)) : 0.f;
        #pragma unroll
        for (int u = 0; u < FIN / 32; u++) {
            int k = u * 32 + lane;
            float v = rp[k];
            if (RB) v = fmaxf(fmaf(v, sinv, sB[k]), 0.f);
            srow[w][k] = v;
        }
        __syncwarp();

        float acc[FOUT / 32];
        #pragma unroll
        for (int c = 0; c < FOUT / 32; c++) acc[c] = 0.f;
        #pragma unroll
        for (int k = 0; k < FIN; k++) {
            float rv = srow[w][k];
            #pragma unroll
            for (int c = 0; c < FOUT / 32; c++)
                acc[c] += rv * sWt[k * FOUT + c * 32 + lane];
        }

        float pa = 0.f, pd = 0.f;
        #pragma unroll
        for (int c = 0; c < FOUT / 32; c++) {
            g_h[(size_t)row * FOUT + c * 32 + lane] = acc[c];
            aggz[(size_t)row * FOUT + c * 32 + lane] = 0.f;
            pa += acc[c] * sA[c * 32 + lane];
            pd += acc[c] * sD[c * 32 + lane];
        }
        #pragma unroll
        for (int o = 16; o > 0; o >>= 1) {
            pa += __shfl_down_sync(0xffffffffu, pa, o);
            pd += __shfl_down_sync(0xffffffffu, pd, o);
        }
        if (lane == 0) { g_as[row] = pa; g_ad[row] = pd; g_s[row] = 0.f; }
        __syncwarp();
    }
}

// ---------------------------------------------------------------------------
// Fused edge pass: per edge compute w = exp(leaky_relu(as[s]+ad[d])),
// accumulate g_s[d] += w, and agg[d] += w * h[s] (UNnormalized).
// FOUT/4 lanes per edge; float4 gather + red.global.add.v4.
// STORE_W: also keep w (layer 1, for alpha output).
// AGG: 1 = g_aggA, 2 = g_aggB.
// ---------------------------------------------------------------------------
template<int FOUT, bool STORE_W, int AGG>
__global__ __launch_bounds__(256)
void edge_scatter(int ep) {
    constexpr int L4 = FOUT / 4;                 // lanes per edge
    int t = blockIdx.x * blockDim.x + threadIdx.x;
    int e = t / L4;
    bool valid = e < ep;
    int ec = valid ? e : (ep - 1);
    int f4 = t % L4;
    int lane = threadIdx.x & 31;
    int base = lane & ~(L4 - 1);

    int s = 0, d = 0;
    float w = 0.f;
    if (f4 == 0) {
        int2 ed = g_edge[ec];
        s = ed.x; d = ed.y;
        float v = g_as[s] + g_ad[d];
        v = v > 0.f ? v : NEG_SLOPE * v;
        w = __expf(v);
        if (valid) {
            atomicAdd(&g_s[d], w);
            if (STORE_W) g_ew[ec] = w;
        }
    }
    s = __shfl_sync(0xffffffffu, s, base);
    d = __shfl_sync(0xffffffffu, d, base);
    w = __shfl_sync(0xffffffffu, w, base);

    const float4 hv = *(const float4*)&g_h[(size_t)s * FOUT + f4 * 4];
    float* agg = (AGG == 1) ? g_aggA : g_aggB;
    if (valid)
        red_add_v4(&agg[(size_t)d * FOUT + f4 * 4],
                   w * hv.x, w * hv.y, w * hv.z, w * hv.w);
}

// ---------------------------------------------------------------------------
// alpha = w / (s[d] + eps)   (layer 1 only; must run before gemm2 zeroes g_s)
// ---------------------------------------------------------------------------
__global__ void alpha_out(int ep, float* __restrict__ outAlpha) {
    int e = blockIdx.x * blockDim.x + threadIdx.x;
    if (e >= ep) return;
    int d = g_edge[e].y;
    outAlpha[e] = g_ew[e] / (g_s[d] + EPS_F);
}

// ---------------------------------------------------------------------------
// Final epilogue: out = aggA * (1/(s+eps)) + b3   (rows of 32 floats)
// ---------------------------------------------------------------------------
__global__ void finalize(int n, const float* __restrict__ b3,
                         float* __restrict__ outO) {
    int t = blockIdx.x * blockDim.x + threadIdx.x;
    if (t >= n * 8) return;
    int r = t >> 3, f4 = t & 7;
    float sinv = 1.f / (g_s[r] + EPS_F);
    float4 a = ((const float4*)g_aggA)[(size_t)r * 8 + f4];
    float4 b = ((const float4*)b3)[f4];
    float4 o;
    o.x = fmaf(a.x, sinv, b.x);
    o.y = fmaf(a.y, sinv, b.y);
    o.z = fmaf(a.z, sinv, b.z);
    o.w = fmaf(a.w, sinv, b.w);
    ((float4*)outO)[(size_t)r * 8 + f4] = o;
}

// ---------------------------------------------------------------------------

extern "C" void kernel_launch(void* const* d_in, const int* in_sizes, int n_in,
                              void* d_out, int out_size) {
    const float* x    = (const float*)d_in[0];
    const int*   ei32 = (const int*)d_in[1];
    const float* W1 = (const float*)d_in[2];
    const float* a1s = (const float*)d_in[3];
    const float* a1d = (const float*)d_in[4];
    const float* b1 = (const float*)d_in[5];
    const float* W2 = (const float*)d_in[6];
    const float* a2s = (const float*)d_in[7];
    const float* a2d = (const float*)d_in[8];
    const float* b2 = (const float*)d_in[9];
    const float* W3 = (const float*)d_in[10];
    const float* a3s = (const float*)d_in[11];
    const float* a3d = (const float*)d_in[12];
    const float* b3 = (const float*)d_in[13];

    const int N  = in_sizes[0] / 128;     // 50000
    const int E  = in_sizes[1] / 2;       // 800000
    const int Ep = E + N;                 // with self loops

    float* out      = (float*)d_out;
    float* outAlpha = out + 2 * (size_t)Ep;
    float* outO     = out + 3 * (size_t)Ep;

    const int TB = 256;
    int ebl = (Ep + TB - 1) / TB;

    detect_dtype<<<1, 32>>>(ei32);
    build_edges<<<ebl, TB>>>(ei32, E, Ep, N, out);

    // ---- layer 1: 128 -> 64, agg into A ----
    gat_gemm<128, 64, false, 0, 1><<<592, TB>>>(x, nullptr, W1, a1s, a1d, N);
    edge_scatter<64, true, 1><<<(int)(((long long)Ep * 16 + TB - 1) / TB), TB>>>(Ep);
    alpha_out<<<ebl, TB>>>(Ep, outAlpha);

    // ---- layer 2: 64 -> 64, in = norm(A), agg into B ----
    gat_gemm<64, 64, true, 1, 2><<<592, TB>>>(nullptr, b1, W2, a2s, a2d, N);
    edge_scatter<64, false, 2><<<(int)(((long long)Ep * 16 + TB - 1) / TB), TB>>>(Ep);

    // ---- layer 3: 64 -> 32, in = norm(B), agg into A ----
    gat_gemm<64, 32, true, 2, 1><<<592, TB>>>(nullptr, b2, W3, a3s, a3d, N);
    edge_scatter<32, false, 1><<<(int)(((long long)Ep * 8 + TB - 1) / TB), TB>>>(Ep);

    finalize<<<(N * 8 + TB - 1) / TB, TB>>>(N, b3, outO);
}

// round 4
// speedup vs baseline: 2.1204x; 1.3124x over previous
#include <cuda_runtime.h>

#define EPS_F 1e-16f
#define NEG_SLOPE 0.2f

static const int MAXN = 50048;
static const int MAXE = 850048;

// scratch (device globals — no allocation allowed)
__device__ __align__(16) int2  g_edge[MAXE];
__device__ int   g_deg[MAXN];
__device__ int   g_off[MAXN + 1];
__device__ int   g_cur[MAXN];
__device__ int   g_csr_src[MAXE];
__device__ int   g_csr_eid[MAXE];
__device__ __align__(16) float g_h[(size_t)MAXN * 64];
__device__ __align__(16) float g_aggA[(size_t)MAXN * 64];
__device__ __align__(16) float g_aggB[(size_t)MAXN * 64];
__device__ float g_as[MAXN];
__device__ float g_ad[MAXN];
__device__ int   g_is64;

// ---------------------------------------------------------------------------
__global__ void detect_dtype(const int* __restrict__ ei32) {
    if (threadIdx.x == 0 && blockIdx.x == 0) {
        int all_zero = 1;
        #pragma unroll
        for (int k = 0; k < 64; k++)
            if (ei32[2 * k + 1] != 0) { all_zero = 0; break; }
        g_is64 = all_zero;
    }
}

__global__ void zero_deg(int n) {
    int i = blockIdx.x * blockDim.x + threadIdx.x;
    if (i < n) g_deg[i] = 0;
}

// ---------------------------------------------------------------------------
// Build packed int2 edges with self-loops; count per-dst degree; emit
// stacked (src,dst) as float at the head of d_out.
// ---------------------------------------------------------------------------
__global__ void build_edges(const int* __restrict__ ei32, int E, int Ep, int n,
                            float* __restrict__ outIdx) {
    int e = blockIdx.x * blockDim.x + threadIdx.x;
    if (e >= Ep) return;
    int s, d;
    if (e < E) {
        if (g_is64) {
            const long long* ei = (const long long*)ei32;
            s = (int)ei[e]; d = (int)ei[E + e];
        } else {
            s = ei32[e]; d = ei32[E + e];
        }
    } else {
        s = d = e - E;
    }
    s = min(max(s, 0), n - 1);
    d = min(max(d, 0), n - 1);
    g_edge[e] = make_int2(s, d);
    atomicAdd(&g_deg[d], 1);
    outIdx[e]      = (float)s;
    outIdx[Ep + e] = (float)d;
}

// ---------------------------------------------------------------------------
// Exclusive prefix sum of g_deg -> g_off (and g_cur). Single 1024-thread
// block, warp-shuffle scan, 2 barriers per 1024-chunk.
// ---------------------------------------------------------------------------
__global__ void scan_offsets(int n) {
    __shared__ int warpsum[32];
    __shared__ int s_carry;
    int tid = threadIdx.x, lane = tid & 31, wid = tid >> 5;
    if (tid == 0) s_carry = 0;
    __syncthreads();
    for (int base = 0; base < n; base += 1024) {
        int i = base + tid;
        int v = (i < n) ? g_deg[i] : 0;
        int incl = v;
        #pragma unroll
        for (int off = 1; off < 32; off <<= 1) {
            int t = __shfl_up_sync(0xffffffffu, incl, off);
            if (lane >= off) incl += t;
        }
        if (lane == 31) warpsum[wid] = incl;
        __syncthreads();
        if (wid == 0) {
            int ws = warpsum[lane];
            int wincl = ws;
            #pragma unroll
            for (int off = 1; off < 32; off <<= 1) {
                int t = __shfl_up_sync(0xffffffffu, wincl, off);
                if (lane >= off) wincl += t;
            }
            warpsum[lane] = wincl - ws;   // exclusive warp offsets
        }
        __syncthreads();
        int excl = incl - v + warpsum[wid] + s_carry;
        if (i < n) { g_off[i] = excl; g_cur[i] = excl; }
        __syncthreads();
        if (tid == 1023) s_carry = excl + v;
        __syncthreads();
    }
    if (tid == 0) g_off[n] = s_carry;
}

__global__ void place_edges(int ep) {
    int e = blockIdx.x * blockDim.x + threadIdx.x;
    if (e >= ep) return;
    int2 ed = g_edge[e];
    int pos = atomicAdd(&g_cur[ed.y], 1);
    g_csr_src[pos] = ed.x;
    g_csr_eid[pos] = e;
}

// ---------------------------------------------------------------------------
// GEMM: h = in @ W^T ; g_as = h.a_src ; g_ad = h.a_dst.
// 4 warps/block, 4 rows/warp, float4 smem loads (FMA-dense).
// INSEL: 0 = xin param, 1 = g_aggA, 2 = g_aggB.
// ---------------------------------------------------------------------------
template<int FIN, int FOUT, int INSEL>
__global__ __launch_bounds__(128)
void gat_gemm(const float* __restrict__ xin, const float* __restrict__ W,
              const float* __restrict__ av, const float* __restrict__ dv,
              int n) {
    constexpr int P = FIN + 4;                    // pad: float4-aligned, bank-spread
    __shared__ float sW[FOUT * P];
    __shared__ __align__(16) float srow[4][4][FIN];
    __shared__ float sA[FOUT];
    __shared__ float sD[FOUT];

    int tid = threadIdx.x;
    for (int i = tid; i < FOUT * FIN; i += 128) {
        int j = i / FIN, k = i % FIN;
        sW[j * P + k] = W[i];
    }
    if (tid < FOUT) { sA[tid] = av[tid]; sD[tid] = dv[tid]; }
    __syncthreads();

    const float* in = (INSEL == 0) ? xin : (INSEL == 1 ? g_aggA : g_aggB);
    int w = tid >> 5, lane = tid & 31;
    int j0 = lane, j1 = 32 + lane;

    for (int row0 = (blockIdx.x * 4 + w) * 4; row0 < n; row0 += gridDim.x * 16) {
        int nr = min(4, n - row0);
        for (int r = 0; r < nr; r++) {
            const float4* rp = (const float4*)(in + (size_t)(row0 + r) * FIN);
            if (FIN == 128) ((float4*)srow[w][r])[lane] = rp[lane];
            else if (lane < FIN / 4) ((float4*)srow[w][r])[lane] = rp[lane];
        }
        __syncwarp();

        float acc[4][FOUT / 32];
        #pragma unroll
        for (int r = 0; r < 4; r++)
            #pragma unroll
            for (int c = 0; c < FOUT / 32; c++) acc[r][c] = 0.f;

        #pragma unroll
        for (int kq = 0; kq < FIN / 4; kq++) {
            float4 w0 = *(const float4*)&sW[j0 * P + kq * 4];
            float4 w1;
            if (FOUT > 32) w1 = *(const float4*)&sW[j1 * P + kq * 4];
            #pragma unroll
            for (int r = 0; r < 4; r++) {
                float4 rv = ((const float4*)srow[w][r])[kq];
                acc[r][0] = fmaf(rv.x, w0.x, acc[r][0]);
                acc[r][0] = fmaf(rv.y, w0.y, acc[r][0]);
                acc[r][0] = fmaf(rv.z, w0.z, acc[r][0]);
                acc[r][0] = fmaf(rv.w, w0.w, acc[r][0]);
                if (FOUT > 32) {
                    acc[r][1] = fmaf(rv.x, w1.x, acc[r][1]);
                    acc[r][1] = fmaf(rv.y, w1.y, acc[r][1]);
                    acc[r][1] = fmaf(rv.z, w1.z, acc[r][1]);
                    acc[r][1] = fmaf(rv.w, w1.w, acc[r][1]);
                }
            }
        }

        for (int r = 0; r < nr; r++) {
            int row = row0 + r;
            float pa, pd;
            g_h[(size_t)row * FOUT + j0] = acc[r][0];
            pa = acc[r][0] * sA[j0];
            pd = acc[r][0] * sD[j0];
            if (FOUT > 32) {
                g_h[(size_t)row * FOUT + j1] = acc[r][1];
                pa = fmaf(acc[r][1], sA[j1], pa);
                pd = fmaf(acc[r][1], sD[j1], pd);
            }
            #pragma unroll
            for (int o = 16; o > 0; o >>= 1) {
                pa += __shfl_down_sync(0xffffffffu, pa, o);
                pd += __shfl_down_sync(0xffffffffu, pd, o);
            }
            if (lane == 0) { g_as[row] = pa; g_ad[row] = pd; }
        }
        __syncwarp();
    }
}

// ---------------------------------------------------------------------------
// CSR gather: warp per dst node. For each incident edge compute
// w = exp(leaky_relu(as[src] + ad[d])), accumulate s += w and acc += w*h[src];
// write ONE output row (no atomics).
// MODE 0 (layer1): out = relu(acc/s + b1) -> g_aggA, plus alpha pass.
// MODE 1 (layer2): out = relu(acc/s + b2) -> g_aggB.
// MODE 2 (layer3): out = acc/s + b3 -> outO.
// ---------------------------------------------------------------------------
template<int FOUT, int MODE>
__global__ __launch_bounds__(256)
void gat_gather(int n, const float* __restrict__ bias,
                float* __restrict__ outAlpha, float* __restrict__ outO) {
    int wg = (blockIdx.x * blockDim.x + threadIdx.x) >> 5;
    int lane = threadIdx.x & 31;
    if (wg >= n) return;
    int d = wg;
    int beg = g_off[d], end = g_off[d + 1];
    float ad = g_ad[d];

    float2 acc = make_float2(0.f, 0.f);
    float acc1 = 0.f;
    float s = 0.f;

    for (int p = beg; p < end; p++) {
        int src = g_csr_src[p];
        float v = g_as[src] + ad;
        v = v > 0.f ? v : NEG_SLOPE * v;
        float wgt = __expf(v);
        s += wgt;
        if (FOUT == 64) {
            float2 hv = *(const float2*)&g_h[(size_t)src * 64 + lane * 2];
            acc.x = fmaf(wgt, hv.x, acc.x);
            acc.y = fmaf(wgt, hv.y, acc.y);
        } else {
            acc1 = fmaf(wgt, g_h[(size_t)src * 32 + lane], acc1);
        }
    }
    float sinv = 1.f / (s + EPS_F);

    if (MODE == 0 || MODE == 1) {
        float* outp = (MODE == 0) ? g_aggA : g_aggB;
        float2 b = *(const float2*)&bias[lane * 2];
        float2 o;
        o.x = fmaxf(fmaf(acc.x, sinv, b.x), 0.f);
        o.y = fmaxf(fmaf(acc.y, sinv, b.y), 0.f);
        *(float2*)&outp[(size_t)d * 64 + lane * 2] = o;
    } else {
        outO[(size_t)d * 32 + lane] = fmaf(acc1, sinv, bias[lane]);
    }

    if (MODE == 0) {
        for (int p = beg + lane; p < end; p += 32) {
            int src = g_csr_src[p];
            float v = g_as[src] + ad;
            v = v > 0.f ? v : NEG_SLOPE * v;
            outAlpha[g_csr_eid[p]] = __expf(v) * sinv;
        }
    }
}

// ---------------------------------------------------------------------------

extern "C" void kernel_launch(void* const* d_in, const int* in_sizes, int n_in,
                              void* d_out, int out_size) {
    const float* x    = (const float*)d_in[0];
    const int*   ei32 = (const int*)d_in[1];
    const float* W1 = (const float*)d_in[2];
    const float* a1s = (const float*)d_in[3];
    const float* a1d = (const float*)d_in[4];
    const float* b1 = (const float*)d_in[5];
    const float* W2 = (const float*)d_in[6];
    const float* a2s = (const float*)d_in[7];
    const float* a2d = (const float*)d_in[8];
    const float* b2 = (const float*)d_in[9];
    const float* W3 = (const float*)d_in[10];
    const float* a3s = (const float*)d_in[11];
    const float* a3d = (const float*)d_in[12];
    const float* b3 = (const float*)d_in[13];

    const int N  = in_sizes[0] / 128;     // 50000
    const int E  = in_sizes[1] / 2;       // 800000
    const int Ep = E + N;                 // with self loops

    float* out      = (float*)d_out;
    float* outAlpha = out + 2 * (size_t)Ep;
    float* outO     = out + 3 * (size_t)Ep;

    const int TB = 256;
    int ebl = (Ep + TB - 1) / TB;
    int gemm_grid = (N + 15) / 16;        // 4 warps x 4 rows per block
    int gath_grid = (N + 7) / 8;          // 8 warps per block, warp per node

    detect_dtype<<<1, 32>>>(ei32);
    zero_deg<<<(N + TB - 1) / TB, TB>>>(N);
    build_edges<<<ebl, TB>>>(ei32, E, Ep, N, out);
    scan_offsets<<<1, 1024>>>(N);
    place_edges<<<ebl, TB>>>(Ep);

    // ---- layer 1: 128 -> 64 ----
    gat_gemm<128, 64, 0><<<gemm_grid, 128>>>(x, W1, a1s, a1d, N);
    gat_gather<64, 0><<<gath_grid, TB>>>(N, b1, outAlpha, nullptr);

    // ---- layer 2: 64 -> 64 ----
    gat_gemm<64, 64, 1><<<gemm_grid, 128>>>(nullptr, W2, a2s, a2d, N);
    gat_gather<64, 1><<<gath_grid, TB>>>(N, b2, nullptr, nullptr);

    // ---- layer 3: 64 -> 32 ----
    gat_gemm<64, 32, 2><<<gemm_grid, 128>>>(nullptr, W3, a3s, a3d, N);
    gat_gather<32, 2><<<gath_grid, TB>>>(N, b3, nullptr, outO);
}

// round 5
// speedup vs baseline: 2.4269x; 1.1446x over previous
#include <cuda_runtime.h>

#define EPS_F 1e-16f
#define NEG_SLOPE 0.2f

static const int MAXN = 50048;
static const int MAXE = 850048;
static const int NBMAX = 64;

// scratch (device globals — no allocation allowed)
__device__ __align__(16) int2  g_edge[MAXE];
__device__ int   g_deg[MAXN];
__device__ int   g_off[MAXN + 1];
__device__ int   g_cur[MAXN];
__device__ int   g_csr_src[MAXE];
__device__ int   g_csr_eid[MAXE];
__device__ int   g_bsum[NBMAX];
__device__ int   g_bexcl[NBMAX];
__device__ __align__(16) float g_h[(size_t)MAXN * 64];
__device__ __align__(16) float g_aggA[(size_t)MAXN * 64];
__device__ __align__(16) float g_aggB[(size_t)MAXN * 64];
__device__ float g_as[MAXN];
__device__ float g_ad[MAXN];
__device__ int   g_is64;

// ---------------------------------------------------------------------------
__global__ void detect_dtype(const int* __restrict__ ei32) {
    if (threadIdx.x == 0 && blockIdx.x == 0) {
        int all_zero = 1;
        #pragma unroll
        for (int k = 0; k < 64; k++)
            if (ei32[2 * k + 1] != 0) { all_zero = 0; break; }
        g_is64 = all_zero;
    }
}

__global__ void zero_deg(int n) {
    int i = blockIdx.x * blockDim.x + threadIdx.x;
    if (i < n) g_deg[i] = 0;
}

// ---------------------------------------------------------------------------
// Build packed int2 edges with self-loops; count per-dst degree; emit
// stacked (src,dst) as float at the head of d_out.
// ---------------------------------------------------------------------------
__global__ void build_edges(const int* __restrict__ ei32, int E, int Ep, int n,
                            float* __restrict__ outIdx) {
    int e = blockIdx.x * blockDim.x + threadIdx.x;
    if (e >= Ep) return;
    int s, d;
    if (e < E) {
        if (g_is64) {
            const long long* ei = (const long long*)ei32;
            s = (int)ei[e]; d = (int)ei[E + e];
        } else {
            s = ei32[e]; d = ei32[E + e];
        }
    } else {
        s = d = e - E;
    }
    s = min(max(s, 0), n - 1);
    d = min(max(d, 0), n - 1);
    g_edge[e] = make_int2(s, d);
    atomicAdd(&g_deg[d], 1);
    outIdx[e]      = (float)s;
    outIdx[Ep + e] = (float)d;
}

// ---------------------------------------------------------------------------
// Multi-block exclusive scan of g_deg -> g_off / g_cur.
// Phase 1: per-block (1024-chunk) sums. Phase 2: scan the <=64 block sums.
// Phase 3: per-block rescan + base offset, write g_off/g_cur.
// ---------------------------------------------------------------------------
__device__ __forceinline__ int block_scan_1024(int v, int lane, int wid,
                                               int* warpsum) {
    int incl = v;
    #pragma unroll
    for (int off = 1; off < 32; off <<= 1) {
        int t = __shfl_up_sync(0xffffffffu, incl, off);
        if (lane >= off) incl += t;
    }
    if (lane == 31) warpsum[wid] = incl;
    __syncthreads();
    if (wid == 0) {
        int ws = warpsum[lane];
        int wincl = ws;
        #pragma unroll
        for (int off = 1; off < 32; off <<= 1) {
            int t = __shfl_up_sync(0xffffffffu, wincl, off);
            if (lane >= off) wincl += t;
        }
        warpsum[lane] = wincl - ws;
    }
    __syncthreads();
    return incl + warpsum[wid];      // inclusive within block
}

__global__ void scan_phase1(int n) {
    __shared__ int warpsum[32];
    int tid = threadIdx.x, lane = tid & 31, wid = tid >> 5;
    int i = blockIdx.x * 1024 + tid;
    int v = (i < n) ? g_deg[i] : 0;
    // reduce only
    #pragma unroll
    for (int off = 16; off > 0; off >>= 1)
        v += __shfl_down_sync(0xffffffffu, v, off);
    if (lane == 0) warpsum[wid] = v;
    __syncthreads();
    if (wid == 0) {
        int t = warpsum[lane];
        #pragma unroll
        for (int off = 16; off > 0; off >>= 1)
            t += __shfl_down_sync(0xffffffffu, t, off);
        if (lane == 0) g_bsum[blockIdx.x] = t;
    }
}

__global__ void scan_phase2(int nb) {
    __shared__ int w0sum;
    int tid = threadIdx.x, lane = tid & 31;   // 64 threads
    int v = (tid < nb) ? g_bsum[tid] : 0;
    int incl = v;
    #pragma unroll
    for (int off = 1; off < 32; off <<= 1) {
        int t = __shfl_up_sync(0xffffffffu, incl, off);
        if (lane >= off) incl += t;
    }
    if (tid == 31) w0sum = incl;
    __syncthreads();
    if (tid >= 32) incl += w0sum;
    g_bexcl[tid] = incl - v;
}

__global__ void scan_phase3(int n) {
    __shared__ int warpsum[32];
    int tid = threadIdx.x, lane = tid & 31, wid = tid >> 5;
    int i = blockIdx.x * 1024 + tid;
    int v = (i < n) ? g_deg[i] : 0;
    int incl = block_scan_1024(v, lane, wid, warpsum);
    int excl = incl - v + g_bexcl[blockIdx.x];
    if (i < n) {
        g_off[i] = excl;
        g_cur[i] = excl;
        if (i == n - 1) g_off[n] = excl + v;
    }
}

__global__ void place_edges(int ep) {
    int e = blockIdx.x * blockDim.x + threadIdx.x;
    if (e >= ep) return;
    int2 ed = g_edge[e];
    int pos = atomicAdd(&g_cur[ed.y], 1);
    g_csr_src[pos] = ed.x;
    g_csr_eid[pos] = e;
}

// ---------------------------------------------------------------------------
// GEMM: h = in @ W^T ; g_as = h.a_src ; g_ad = h.a_dst.
// 4 warps/block, 4 rows/warp, float4 smem loads (FMA-dense).
// INSEL: 0 = xin param, 1 = g_aggA, 2 = g_aggB.
// ---------------------------------------------------------------------------
template<int FIN, int FOUT, int INSEL>
__global__ __launch_bounds__(128)
void gat_gemm(const float* __restrict__ xin, const float* __restrict__ W,
              const float* __restrict__ av, const float* __restrict__ dv,
              int n) {
    constexpr int P = FIN + 4;
    __shared__ float sW[FOUT * P];
    __shared__ __align__(16) float srow[4][4][FIN];
    __shared__ float sA[FOUT];
    __shared__ float sD[FOUT];

    int tid = threadIdx.x;
    for (int i = tid; i < FOUT * FIN; i += 128) {
        int j = i / FIN, k = i % FIN;
        sW[j * P + k] = W[i];
    }
    if (tid < FOUT) { sA[tid] = av[tid]; sD[tid] = dv[tid]; }
    __syncthreads();

    const float* in = (INSEL == 0) ? xin : (INSEL == 1 ? g_aggA : g_aggB);
    int w = tid >> 5, lane = tid & 31;
    int j0 = lane, j1 = 32 + lane;

    for (int row0 = (blockIdx.x * 4 + w) * 4; row0 < n; row0 += gridDim.x * 16) {
        int nr = min(4, n - row0);
        for (int r = 0; r < nr; r++) {
            const float4* rp = (const float4*)(in + (size_t)(row0 + r) * FIN);
            if (FIN == 128) ((float4*)srow[w][r])[lane] = rp[lane];
            else if (lane < FIN / 4) ((float4*)srow[w][r])[lane] = rp[lane];
        }
        __syncwarp();

        float acc[4][FOUT / 32];
        #pragma unroll
        for (int r = 0; r < 4; r++)
            #pragma unroll
            for (int c = 0; c < FOUT / 32; c++) acc[r][c] = 0.f;

        #pragma unroll
        for (int kq = 0; kq < FIN / 4; kq++) {
            float4 w0 = *(const float4*)&sW[j0 * P + kq * 4];
            float4 w1;
            if (FOUT > 32) w1 = *(const float4*)&sW[j1 * P + kq * 4];
            #pragma unroll
            for (int r = 0; r < 4; r++) {
                float4 rv = ((const float4*)srow[w][r])[kq];
                acc[r][0] = fmaf(rv.x, w0.x, acc[r][0]);
                acc[r][0] = fmaf(rv.y, w0.y, acc[r][0]);
                acc[r][0] = fmaf(rv.z, w0.z, acc[r][0]);
                acc[r][0] = fmaf(rv.w, w0.w, acc[r][0]);
                if (FOUT > 32) {
                    acc[r][1] = fmaf(rv.x, w1.x, acc[r][1]);
                    acc[r][1] = fmaf(rv.y, w1.y, acc[r][1]);
                    acc[r][1] = fmaf(rv.z, w1.z, acc[r][1]);
                    acc[r][1] = fmaf(rv.w, w1.w, acc[r][1]);
                }
            }
        }

        for (int r = 0; r < nr; r++) {
            int row = row0 + r;
            float pa, pd;
            g_h[(size_t)row * FOUT + j0] = acc[r][0];
            pa = acc[r][0] * sA[j0];
            pd = acc[r][0] * sD[j0];
            if (FOUT > 32) {
                g_h[(size_t)row * FOUT + j1] = acc[r][1];
                pa = fmaf(acc[r][1], sA[j1], pa);
                pd = fmaf(acc[r][1], sD[j1], pd);
            }
            #pragma unroll
            for (int o = 16; o > 0; o >>= 1) {
                pa += __shfl_down_sync(0xffffffffu, pa, o);
                pd += __shfl_down_sync(0xffffffffu, pd, o);
            }
            if (lane == 0) { g_as[row] = pa; g_ad[row] = pd; }
        }
        __syncwarp();
    }
}

// ---------------------------------------------------------------------------
// CSR gather: warp per dst node. Per 32-edge batch: lane q coalesced-loads
// csr_src[p0+q] and computes its own edge weight (ONE scattered g_as load
// per lane per batch); inner loop shuffles (src, w) and only gathers h rows.
// MODE 0 (layer1): out = relu(acc/s + b1) -> g_aggA, plus alpha pass.
// MODE 1 (layer2): out = relu(acc/s + b2) -> g_aggB.
// MODE 2 (layer3): out = acc/s + b3 -> outO.
// ---------------------------------------------------------------------------
template<int FOUT, int MODE>
__global__ __launch_bounds__(256)
void gat_gather(int n, const float* __restrict__ bias,
                float* __restrict__ outAlpha, float* __restrict__ outO) {
    int wg = (blockIdx.x * blockDim.x + threadIdx.x) >> 5;
    int lane = threadIdx.x & 31;
    if (wg >= n) return;
    int d = wg;
    int beg = g_off[d], end = g_off[d + 1];
    float ad = g_ad[d];

    float2 acc = make_float2(0.f, 0.f);
    float acc1 = 0.f;
    float s = 0.f;

    for (int p0 = beg; p0 < end; p0 += 32) {
        int cnt = min(32, end - p0);
        int src_l = 0;
        float w_l = 0.f;
        if (lane < cnt) {
            src_l = g_csr_src[p0 + lane];
            float v = g_as[src_l] + ad;
            v = v > 0.f ? v : NEG_SLOPE * v;
            w_l = __expf(v);
        }
        #pragma unroll 4
        for (int q = 0; q < cnt; q++) {
            int src   = __shfl_sync(0xffffffffu, src_l, q);
            float wgt = __shfl_sync(0xffffffffu, w_l, q);
            s += wgt;
            if (FOUT == 64) {
                float2 hv = *(const float2*)&g_h[(size_t)src * 64 + lane * 2];
                acc.x = fmaf(wgt, hv.x, acc.x);
                acc.y = fmaf(wgt, hv.y, acc.y);
            } else {
                acc1 = fmaf(wgt, g_h[(size_t)src * 32 + lane], acc1);
            }
        }
    }
    float sinv = 1.f / (s + EPS_F);

    if (MODE == 0 || MODE == 1) {
        float* outp = (MODE == 0) ? g_aggA : g_aggB;
        float2 b = *(const float2*)&bias[lane * 2];
        float2 o;
        o.x = fmaxf(fmaf(acc.x, sinv, b.x), 0.f);
        o.y = fmaxf(fmaf(acc.y, sinv, b.y), 0.f);
        *(float2*)&outp[(size_t)d * 64 + lane * 2] = o;
    } else {
        outO[(size_t)d * 32 + lane] = fmaf(acc1, sinv, bias[lane]);
    }

    if (MODE == 0) {
        for (int p = beg + lane; p < end; p += 32) {
            int src = g_csr_src[p];
            float v = g_as[src] + ad;
            v = v > 0.f ? v : NEG_SLOPE * v;
            outAlpha[g_csr_eid[p]] = __expf(v) * sinv;
        }
    }
}

// ---------------------------------------------------------------------------

extern "C" void kernel_launch(void* const* d_in, const int* in_sizes, int n_in,
                              void* d_out, int out_size) {
    const float* x    = (const float*)d_in[0];
    const int*   ei32 = (const int*)d_in[1];
    const float* W1 = (const float*)d_in[2];
    const float* a1s = (const float*)d_in[3];
    const float* a1d = (const float*)d_in[4];
    const float* b1 = (const float*)d_in[5];
    const float* W2 = (const float*)d_in[6];
    const float* a2s = (const float*)d_in[7];
    const float* a2d = (const float*)d_in[8];
    const float* b2 = (const float*)d_in[9];
    const float* W3 = (const float*)d_in[10];
    const float* a3s = (const float*)d_in[11];
    const float* a3d = (const float*)d_in[12];
    const float* b3 = (const float*)d_in[13];

    const int N  = in_sizes[0] / 128;     // 50000
    const int E  = in_sizes[1] / 2;       // 800000
    const int Ep = E + N;                 // with self loops

    float* out      = (float*)d_out;
    float* outAlpha = out + 2 * (size_t)Ep;
    float* outO     = out + 3 * (size_t)Ep;

    const int TB = 256;
    int ebl = (Ep + TB - 1) / TB;
    int nb = (N + 1023) / 1024;
    int gemm_grid = (N + 15) / 16;
    int gath_grid = (N + 7) / 8;

    detect_dtype<<<1, 32>>>(ei32);
    zero_deg<<<(N + TB - 1) / TB, TB>>>(N);
    build_edges<<<ebl, TB>>>(ei32, E, Ep, N, out);
    scan_phase1<<<nb, 1024>>>(N);
    scan_phase2<<<1, 64>>>(nb);
    scan_phase3<<<nb, 1024>>>(N);
    place_edges<<<ebl, TB>>>(Ep);

    // ---- layer 1: 128 -> 64 ----
    gat_gemm<128, 64, 0><<<gemm_grid, 128>>>(x, W1, a1s, a1d, N);
    gat_gather<64, 0><<<gath_grid, TB>>>(N, b1, outAlpha, nullptr);

    // ---- layer 2: 64 -> 64 ----
    gat_gemm<64, 64, 1><<<gemm_grid, 128>>>(nullptr, W2, a2s, a2d, N);
    gat_gather<64, 1><<<gath_grid, TB>>>(N, b2, nullptr, nullptr);

    // ---- layer 3: 64 -> 32 ----
    gat_gemm<64, 32, 2><<<gemm_grid, 128>>>(nullptr, W3, a3s, a3d, N);
    gat_gather<32, 2><<<gath_grid, TB>>>(N, b3, nullptr, outO);
}

// round 6
// speedup vs baseline: 2.6388x; 1.0873x over previous
#include <cuda_runtime.h>

#define EPS_F 1e-16f
#define NEG_SLOPE 0.2f

static const int MAXN = 50048;
static const int MAXE = 850048;
static const int NBMAX = 64;

// scratch (device globals — no allocation allowed)
__device__ int   g_deg[MAXN];
__device__ int   g_off[MAXN + 1];
__device__ int   g_cur[MAXN];
__device__ int   g_csr_src[MAXE];
__device__ int   g_csr_eid[MAXE];
__device__ float g_ew[MAXE];
__device__ int   g_bsum[NBMAX];
__device__ __align__(16) float g_h[(size_t)MAXN * 64];
__device__ __align__(16) float g_aggA[(size_t)MAXN * 64];
__device__ __align__(16) float g_aggB[(size_t)MAXN * 64];
__device__ float g_as[MAXN];
__device__ float g_ad[MAXN];
__device__ int   g_is64;

// ---------------------------------------------------------------------------
// init: zero degree array; block 0 also detects edge dtype (int64 vs int32).
// ---------------------------------------------------------------------------
__global__ void init_kernel(const int* __restrict__ ei32, int n) {
    int i = blockIdx.x * blockDim.x + threadIdx.x;
    if (i < n) g_deg[i] = 0;
    if (blockIdx.x == 0 && threadIdx.x == 0) {
        int all_zero = 1;
        #pragma unroll
        for (int k = 0; k < 64; k++)
            if (ei32[2 * k + 1] != 0) { all_zero = 0; break; }
        g_is64 = all_zero;
    }
}

// ---------------------------------------------------------------------------
__device__ __forceinline__ void load_edge(const int* __restrict__ ei32,
                                          int e, int E, int n, int& s, int& d) {
    if (e < E) {
        if (g_is64) {
            const long long* ei = (const long long*)ei32;
            s = (int)ei[e]; d = (int)ei[E + e];
        } else {
            s = ei32[e]; d = ei32[E + e];
        }
    } else {
        s = d = e - E;   // self loop
    }
    s = min(max(s, 0), n - 1);
    d = min(max(d, 0), n - 1);
}

// Count per-dst degree; emit stacked (src,dst) as float at head of d_out.
__global__ void build_edges(const int* __restrict__ ei32, int E, int Ep, int n,
                            float* __restrict__ outIdx) {
    int e = blockIdx.x * blockDim.x + threadIdx.x;
    if (e >= Ep) return;
    int s, d;
    load_edge(ei32, e, E, n, s, d);
    atomicAdd(&g_deg[d], 1);
    outIdx[e]      = (float)s;
    outIdx[Ep + e] = (float)d;
}

// ---------------------------------------------------------------------------
// Scan: phase1 = per-1024-chunk sums; phase3 = per-chunk scan + self base.
// ---------------------------------------------------------------------------
__global__ void scan_phase1(int n) {
    __shared__ int warpsum[32];
    int tid = threadIdx.x, lane = tid & 31, wid = tid >> 5;
    int i = blockIdx.x * 1024 + tid;
    int v = (i < n) ? g_deg[i] : 0;
    #pragma unroll
    for (int off = 16; off > 0; off >>= 1)
        v += __shfl_down_sync(0xffffffffu, v, off);
    if (lane == 0) warpsum[wid] = v;
    __syncthreads();
    if (wid == 0) {
        int t = warpsum[lane];
        #pragma unroll
        for (int off = 16; off > 0; off >>= 1)
            t += __shfl_down_sync(0xffffffffu, t, off);
        if (lane == 0) g_bsum[blockIdx.x] = t;
    }
}

__global__ void scan_phase3(int n) {
    __shared__ int warpsum[32];
    __shared__ int s_base;
    int tid = threadIdx.x, lane = tid & 31, wid = tid >> 5;
    if (tid == 0) {
        int b = 0;
        for (int i = 0; i < blockIdx.x; i++) b += g_bsum[i];
        s_base = b;
    }
    int i = blockIdx.x * 1024 + tid;
    int v = (i < n) ? g_deg[i] : 0;
    int incl = v;
    #pragma unroll
    for (int off = 1; off < 32; off <<= 1) {
        int t = __shfl_up_sync(0xffffffffu, incl, off);
        if (lane >= off) incl += t;
    }
    if (lane == 31) warpsum[wid] = incl;
    __syncthreads();
    if (wid == 0) {
        int ws = warpsum[lane];
        int wincl = ws;
        #pragma unroll
        for (int off = 1; off < 32; off <<= 1) {
            int t = __shfl_up_sync(0xffffffffu, wincl, off);
            if (lane >= off) wincl += t;
        }
        warpsum[lane] = wincl - ws;
    }
    __syncthreads();
    int excl = incl - v + warpsum[wid] + s_base;
    if (i < n) {
        g_off[i] = excl;
        g_cur[i] = excl;
        if (i == n - 1) g_off[n] = excl + v;
    }
}

__global__ void place_edges(const int* __restrict__ ei32, int E, int Ep, int n) {
    int e = blockIdx.x * blockDim.x + threadIdx.x;
    if (e >= Ep) return;
    int s, d;
    load_edge(ei32, e, E, n, s, d);
    int pos = atomicAdd(&g_cur[d], 1);
    g_csr_src[pos] = s;
    g_csr_eid[pos] = e;
}

// ---------------------------------------------------------------------------
// GEMM: h = in @ W^T ; g_as = h.a_src ; g_ad = h.a_dst.
// 4 warps/block, 4 rows/warp, float4 smem loads (FMA-dense).
// INSEL: 0 = xin param, 1 = g_aggA, 2 = g_aggB.
// ---------------------------------------------------------------------------
template<int FIN, int FOUT, int INSEL>
__global__ __launch_bounds__(128)
void gat_gemm(const float* __restrict__ xin, const float* __restrict__ W,
              const float* __restrict__ av, const float* __restrict__ dv,
              int n) {
    constexpr int P = FIN + 4;
    __shared__ float sW[FOUT * P];
    __shared__ __align__(16) float srow[4][4][FIN];
    __shared__ float sA[FOUT];
    __shared__ float sD[FOUT];

    int tid = threadIdx.x;
    for (int i = tid; i < FOUT * FIN; i += 128) {
        int j = i / FIN, k = i % FIN;
        sW[j * P + k] = W[i];
    }
    if (tid < FOUT) { sA[tid] = av[tid]; sD[tid] = dv[tid]; }
    __syncthreads();

    const float* in = (INSEL == 0) ? xin : (INSEL == 1 ? g_aggA : g_aggB);
    int w = tid >> 5, lane = tid & 31;
    int j0 = lane, j1 = 32 + lane;

    for (int row0 = (blockIdx.x * 4 + w) * 4; row0 < n; row0 += gridDim.x * 16) {
        int nr = min(4, n - row0);
        for (int r = 0; r < nr; r++) {
            const float4* rp = (const float4*)(in + (size_t)(row0 + r) * FIN);
            if (FIN == 128) ((float4*)srow[w][r])[lane] = rp[lane];
            else if (lane < FIN / 4) ((float4*)srow[w][r])[lane] = rp[lane];
        }
        __syncwarp();

        float acc[4][FOUT / 32];
        #pragma unroll
        for (int r = 0; r < 4; r++)
            #pragma unroll
            for (int c = 0; c < FOUT / 32; c++) acc[r][c] = 0.f;

        #pragma unroll
        for (int kq = 0; kq < FIN / 4; kq++) {
            float4 w0 = *(const float4*)&sW[j0 * P + kq * 4];
            float4 w1;
            if (FOUT > 32) w1 = *(const float4*)&sW[j1 * P + kq * 4];
            #pragma unroll
            for (int r = 0; r < 4; r++) {
                float4 rv = ((const float4*)srow[w][r])[kq];
                acc[r][0] = fmaf(rv.x, w0.x, acc[r][0]);
                acc[r][0] = fmaf(rv.y, w0.y, acc[r][0]);
                acc[r][0] = fmaf(rv.z, w0.z, acc[r][0]);
                acc[r][0] = fmaf(rv.w, w0.w, acc[r][0]);
                if (FOUT > 32) {
                    acc[r][1] = fmaf(rv.x, w1.x, acc[r][1]);
                    acc[r][1] = fmaf(rv.y, w1.y, acc[r][1]);
                    acc[r][1] = fmaf(rv.z, w1.z, acc[r][1]);
                    acc[r][1] = fmaf(rv.w, w1.w, acc[r][1]);
                }
            }
        }

        for (int r = 0; r < nr; r++) {
            int row = row0 + r;
            float pa, pd;
            g_h[(size_t)row * FOUT + j0] = acc[r][0];
            pa = acc[r][0] * sA[j0];
            pd = acc[r][0] * sD[j0];
            if (FOUT > 32) {
                g_h[(size_t)row * FOUT + j1] = acc[r][1];
                pa = fmaf(acc[r][1], sA[j1], pa);
                pd = fmaf(acc[r][1], sD[j1], pd);
            }
            #pragma unroll
            for (int o = 16; o > 0; o >>= 1) {
                pa += __shfl_down_sync(0xffffffffu, pa, o);
                pd += __shfl_down_sync(0xffffffffu, pd, o);
            }
            if (lane == 0) { g_as[row] = pa; g_ad[row] = pd; }
        }
        __syncwarp();
    }
}

// ---------------------------------------------------------------------------
// CSR gather v2: warp per dst node, group-per-edge float4 layout.
// FOUT=64 -> 2 groups of 16 lanes (2 edges/iter, LDG.128);
// FOUT=32 -> 4 groups of 8 lanes (4 edges/iter).
// Per 32-edge batch: lane q loads csr_src[p0+q] and computes its own edge
// weight (one scattered g_as load / lane); MODE 0 stores w coalesced to g_ew.
// MODE 0 (layer1): out = relu(acc/s + b1) -> g_aggA, plus coalesced alpha.
// MODE 1 (layer2): out = relu(acc/s + b2) -> g_aggB.
// MODE 2 (layer3): out = acc/s + b3 -> outO.
// ---------------------------------------------------------------------------
template<int FOUT, int MODE>
__global__ __launch_bounds__(256)
void gat_gather(int n, const float* __restrict__ bias,
                float* __restrict__ outAlpha, float* __restrict__ outO) {
    constexpr int GSZ = FOUT / 4;      // lanes per group
    constexpr int NG  = 32 / GSZ;      // edges per iteration
    int wg = (blockIdx.x * blockDim.x + threadIdx.x) >> 5;
    int lane = threadIdx.x & 31;
    if (wg >= n) return;
    int d = wg;
    int beg = g_off[d], end = g_off[d + 1];
    float ad = g_ad[d];
    int g = lane / GSZ, fl = lane % GSZ;

    float4 acc = make_float4(0.f, 0.f, 0.f, 0.f);
    float s = 0.f;

    for (int p0 = beg; p0 < end; p0 += 32) {
        int cnt = min(32, end - p0);
        int src_l = 0;
        float w_l = 0.f;
        if (lane < cnt) {
            src_l = g_csr_src[p0 + lane];
            float v = g_as[src_l] + ad;
            v = v > 0.f ? v : NEG_SLOPE * v;
            w_l = __expf(v);
            if (MODE == 0) g_ew[p0 + lane] = w_l;
        }
        #pragma unroll 2
        for (int q = 0; q < cnt; q += NG) {
            int idx = q + g;
            float wh  = __shfl_sync(0xffffffffu, w_l, idx & 31);
            int  srch = __shfl_sync(0xffffffffu, src_l, idx & 31);
            float w2 = (idx < cnt) ? wh : 0.f;
            float4 hv = *(const float4*)&g_h[(size_t)srch * FOUT + fl * 4];
            acc.x = fmaf(w2, hv.x, acc.x);
            acc.y = fmaf(w2, hv.y, acc.y);
            acc.z = fmaf(w2, hv.z, acc.z);
            acc.w = fmaf(w2, hv.w, acc.w);
            s += w2;
        }
    }
    // combine groups
    #pragma unroll
    for (int off = GSZ; off < 32; off <<= 1) {
        s     += __shfl_xor_sync(0xffffffffu, s, off);
        acc.x += __shfl_xor_sync(0xffffffffu, acc.x, off);
        acc.y += __shfl_xor_sync(0xffffffffu, acc.y, off);
        acc.z += __shfl_xor_sync(0xffffffffu, acc.z, off);
        acc.w += __shfl_xor_sync(0xffffffffu, acc.w, off);
    }
    float sinv = 1.f / (s + EPS_F);

    if (lane < GSZ) {
        float4 b = *(const float4*)&bias[fl * 4];
        float4 o;
        if (MODE == 2) {
            o.x = fmaf(acc.x, sinv, b.x);
            o.y = fmaf(acc.y, sinv, b.y);
            o.z = fmaf(acc.z, sinv, b.z);
            o.w = fmaf(acc.w, sinv, b.w);
            *(float4*)&outO[(size_t)d * FOUT + fl * 4] = o;
        } else {
            o.x = fmaxf(fmaf(acc.x, sinv, b.x), 0.f);
            o.y = fmaxf(fmaf(acc.y, sinv, b.y), 0.f);
            o.z = fmaxf(fmaf(acc.z, sinv, b.z), 0.f);
            o.w = fmaxf(fmaf(acc.w, sinv, b.w), 0.f);
            float* outp = (MODE == 0) ? g_aggA : g_aggB;
            *(float4*)&outp[(size_t)d * FOUT + fl * 4] = o;
        }
    }

    if (MODE == 0) {
        for (int p = beg + lane; p < end; p += 32)
            outAlpha[g_csr_eid[p]] = g_ew[p] * sinv;
    }
}

// ---------------------------------------------------------------------------

extern "C" void kernel_launch(void* const* d_in, const int* in_sizes, int n_in,
                              void* d_out, int out_size) {
    const float* x    = (const float*)d_in[0];
    const int*   ei32 = (const int*)d_in[1];
    const float* W1 = (const float*)d_in[2];
    const float* a1s = (const float*)d_in[3];
    const float* a1d = (const float*)d_in[4];
    const float* b1 = (const float*)d_in[5];
    const float* W2 = (const float*)d_in[6];
    const float* a2s = (const float*)d_in[7];
    const float* a2d = (const float*)d_in[8];
    const float* b2 = (const float*)d_in[9];
    const float* W3 = (const float*)d_in[10];
    const float* a3s = (const float*)d_in[11];
    const float* a3d = (const float*)d_in[12];
    const float* b3 = (const float*)d_in[13];

    const int N  = in_sizes[0] / 128;     // 50000
    const int E  = in_sizes[1] / 2;       // 800000
    const int Ep = E + N;                 // with self loops

    float* out      = (float*)d_out;
    float* outAlpha = out + 2 * (size_t)Ep;
    float* outO     = out + 3 * (size_t)Ep;

    const int TB = 256;
    int ebl = (Ep + TB - 1) / TB;
    int nb = (N + 1023) / 1024;
    int gemm_grid = (N + 15) / 16;
    int gath_grid = (N + 7) / 8;

    // one-time side-stream for overlapping GEMM1 with preprocessing
    static cudaStream_t s2 = nullptr;
    static cudaEvent_t evFork = nullptr, evJoin = nullptr;
    if (!s2) {
        cudaStreamCreateWithFlags(&s2, cudaStreamNonBlocking);
        cudaEventCreateWithFlags(&evFork, cudaEventDisableTiming);
        cudaEventCreateWithFlags(&evJoin, cudaEventDisableTiming);
    }

    // fork: GEMM1 runs on s2, independent of edge preprocessing
    cudaEventRecord(evFork, 0);
    cudaStreamWaitEvent(s2, evFork, 0);
    gat_gemm<128, 64, 0><<<gemm_grid, 128, 0, s2>>>(x, W1, a1s, a1d, N);
    cudaEventRecord(evJoin, s2);

    // preprocessing chain on main stream
    init_kernel<<<(N + TB - 1) / TB, TB>>>(ei32, N);
    build_edges<<<ebl, TB>>>(ei32, E, Ep, N, out);
    scan_phase1<<<nb, 1024>>>(N);
    scan_phase3<<<nb, 1024>>>(N);
    place_edges<<<ebl, TB>>>(ei32, E, Ep, N);

    // join: gather1 needs both CSR and GEMM1 results
    cudaStreamWaitEvent(0, evJoin, 0);

    // ---- layer 1: 128 -> 64 ----
    gat_gather<64, 0><<<gath_grid, TB>>>(N, b1, outAlpha, nullptr);

    // ---- layer 2: 64 -> 64 ----
    gat_gemm<64, 64, 1><<<gemm_grid, 128>>>(nullptr, W2, a2s, a2d, N);
    gat_gather<64, 1><<<gath_grid, TB>>>(N, b2, nullptr, nullptr);

    // ---- layer 3: 64 -> 32 ----
    gat_gemm<64, 32, 2><<<gemm_grid, 128>>>(nullptr, W3, a3s, a3d, N);
    gat_gather<32, 2><<<gath_grid, TB>>>(N, b3, nullptr, outO);
}